// round 14
// baseline (speedup 1.0000x reference)
#include <cuda_runtime.h>
#include <cuda_fp16.h>
#include <cstdint>
#include <cstddef>

// ---------------------------------------------------------------------------
// CausalSelfAttention: out = proj( causal_attn( x @ Wqkv^T ) )
// fp16 mma.sync m16n8k16.
// GEMM: block 128x256, warp tile 64x64, TBKH=64, 4-stage cp.async ring,
//       fragment double-buffering (smem-traffic-optimal; 1 CTA/SM).
// Attention: fp16 flash, 128-kv stages, f16x2 exp, ones-MMA row sums (R13).
// ---------------------------------------------------------------------------

#define BATCH   4
#define S_LEN   2048
#define D_MODEL 1024
#define D3      3072
#define N_HEADS 16
#define DH      64
#define M_ROWS  (BATCH * S_LEN)   // 8192

__device__ __half g_qkv[(size_t)M_ROWS * D3];
__device__ __half g_y[(size_t)M_ROWS * D_MODEL];
__device__ __half g_xc[(size_t)M_ROWS * D_MODEL];
__device__ __half g_wac[(size_t)D3 * D_MODEL];
__device__ __half g_wpc[(size_t)D_MODEL * D_MODEL];

// ---- helpers ----------------------------------------------------------------
__device__ __forceinline__ uint32_t pack_h2(float a, float b) {
    __half2 h = __floats2half2_rn(a, b);
    return *(uint32_t*)&h;
}
__device__ __forceinline__ float ex2f(float x) {
    float r;
    asm("ex2.approx.ftz.f32 %0, %1;" : "=f"(r) : "f"(x));
    return r;
}
__device__ __forceinline__ uint32_t h2ex2(uint32_t x) {
    uint32_t r;
    asm("ex2.approx.f16x2 %0, %1;" : "=r"(r) : "r"(x));
    return r;
}
__device__ __forceinline__ void ldsm_x4(uint32_t addr, uint32_t& r0, uint32_t& r1,
                                        uint32_t& r2, uint32_t& r3) {
    asm volatile("ldmatrix.sync.aligned.m8n8.x4.shared.b16 {%0,%1,%2,%3}, [%4];"
                 : "=r"(r0), "=r"(r1), "=r"(r2), "=r"(r3) : "r"(addr));
}
__device__ __forceinline__ void ldsm_x4t(uint32_t addr, uint32_t& r0, uint32_t& r1,
                                         uint32_t& r2, uint32_t& r3) {
    asm volatile("ldmatrix.sync.aligned.m8n8.x4.trans.shared.b16 {%0,%1,%2,%3}, [%4];"
                 : "=r"(r0), "=r"(r1), "=r"(r2), "=r"(r3) : "r"(addr));
}
__device__ __forceinline__ void mma_f16(float& c0, float& c1, float& c2, float& c3,
                                        uint32_t a0, uint32_t a1, uint32_t a2, uint32_t a3,
                                        uint32_t b0, uint32_t b1) {
    asm volatile("mma.sync.aligned.m16n8k16.row.col.f32.f16.f16.f32 "
                 "{%0,%1,%2,%3}, {%4,%5,%6,%7}, {%8,%9}, {%0,%1,%2,%3};"
                 : "+f"(c0), "+f"(c1), "+f"(c2), "+f"(c3)
                 : "r"(a0), "r"(a1), "r"(a2), "r"(a3), "r"(b0), "r"(b1));
}
__device__ __forceinline__ void cp16(uint32_t dst, const void* src) {
    asm volatile("cp.async.cg.shared.global [%0], [%1], 16;" :: "r"(dst), "l"(src));
}
#define CP_COMMIT() asm volatile("cp.async.commit_group;")
#define CP_WAIT(n)  asm volatile("cp.async.wait_group %0;" :: "n"(n))

__device__ __forceinline__ uint32_t smem_u32(const void* p) {
    return (uint32_t)__cvta_generic_to_shared(p);
}

// ---------------------------------------------------------------------------
// Fused pre-round fp32 -> fp16 for x, w_attn, w_proj (one launch)
// ---------------------------------------------------------------------------
#define XC_N4  (M_ROWS * D_MODEL / 4)
#define WAC_N4 (D3 * D_MODEL / 4)
#define WPC_N4 (D_MODEL * D_MODEL / 4)
#define RND_TOTAL (XC_N4 + WAC_N4 + WPC_N4)

__global__ void round_all(const float* __restrict__ x, const float* __restrict__ wa,
                          const float* __restrict__ wp) {
    int i = blockIdx.x * blockDim.x + threadIdx.x;
    if (i >= RND_TOTAL) return;
    const float* src;
    __half* dst;
    int j;
    if (i < XC_N4)                { src = x;  dst = g_xc;  j = i; }
    else if (i < XC_N4 + WAC_N4)  { src = wa; dst = g_wac; j = i - XC_N4; }
    else                          { src = wp; dst = g_wpc; j = i - XC_N4 - WAC_N4; }
    float4 v = ((const float4*)src)[j];
    uint2 r = {pack_h2(v.x, v.y), pack_h2(v.z, v.w)};
    ((uint2*)dst)[j] = r;
}

// ---------------------------------------------------------------------------
// fp16 GEMM (NT): C[M,N] = A[M,K] @ B[N,K]^T
// Block 128x256, 8 warps 2(m)x4(n), warp tile 64x64, TBKH=64 (128B rows,
// swizzle ch^(row&7)), 4-stage ring, fragment double-buffer across ks.
// Ordering: CP_WAIT(2) -> sync -> prefetch(it+3) -> commit -> compute.
// ---------------------------------------------------------------------------
#define TBM 128
#define TBN 256
#define TBKH 64
#define GSTG 4
#define GA_BYTES 16384                       // 128 rows x 128B
#define GB_BYTES 32768                       // 256 rows x 128B
#define G_STAGE_BYTES (GA_BYTES + GB_BYTES)  // 49152
#define GEMM_SMEM (GSTG * G_STAGE_BYTES)     // 196608

template <bool HALF_OUT>
__global__ __launch_bounds__(256)
void gemm_f16(const __half* __restrict__ A, const __half* __restrict__ B,
              void* __restrict__ Cv, int M, int N, int K) {
    extern __shared__ uint32_t sh[];

    const int tid    = threadIdx.x;
    const int lane   = tid & 31;
    const int warp   = tid >> 5;
    const int warp_m = warp >> 2;      // 0..1
    const int warp_n = warp & 3;       // 0..3
    const int row0   = blockIdx.y * TBM;
    const int col0   = blockIdx.x * TBN;

    const __half* Ab = A + (size_t)row0 * K;
    const __half* Bb = B + (size_t)col0 * K;

    const uint32_t base = smem_u32(sh);
    uint32_t sA[GSTG], sB[GSTG];
#pragma unroll
    for (int s = 0; s < GSTG; s++) { sA[s] = base + s * G_STAGE_BYTES; sB[s] = sA[s] + GA_BYTES; }

    // cp.async mapping: A 128x8chunks=1024 (4/thr), B 256x8=2048 (8/thr)
    uint32_t la_rel[4], la_off[4];
#pragma unroll
    for (int r = 0; r < 4; r++) {
        int idx = tid + 256 * r, row = idx >> 3, c = idx & 7;
        la_rel[r] = (uint32_t)(row * 128 + ((c ^ (row & 7)) << 4));
        la_off[r] = (uint32_t)(row * K + c * 8);
    }
    uint32_t lb_rel[8], lb_off[8];
#pragma unroll
    for (int r = 0; r < 8; r++) {
        int idx = tid + 256 * r, row = idx >> 3, c = idx & 7;
        lb_rel[r] = (uint32_t)(row * 128 + ((c ^ (row & 7)) << 4));
        lb_off[r] = (uint32_t)(row * K + c * 8);
    }

    // ldsm row constants
    const int mat = lane >> 3, rr = lane & 7;
    uint32_t a_rowOff[4]; int a_rx[4];
#pragma unroll
    for (int mt = 0; mt < 4; mt++) {
        int row = warp_m * 64 + mt * 16 + ((mat & 1) << 3) + rr;
        a_rowOff[mt] = (uint32_t)(row * 128);
        a_rx[mt] = row & 7;
    }
    const int abit = mat >> 1;
    uint32_t b_rowOff[4]; int b_rx[4];
#pragma unroll
    for (int ntp = 0; ntp < 4; ntp++) {
        int row = warp_n * 64 + ntp * 16 + ((mat >> 1) << 3) + rr;
        b_rowOff[ntp] = (uint32_t)(row * 128);
        b_rx[ntp] = row & 7;
    }
    const int bbit = mat & 1;

    float c[4][8][4];
#pragma unroll
    for (int i = 0; i < 4; i++)
#pragma unroll
        for (int j = 0; j < 8; j++)
#pragma unroll
            for (int q = 0; q < 4; q++) c[i][j][q] = 0.f;

    const int NIT = K / TBKH;   // 16

    // prologue: stages 0..2
#pragma unroll
    for (int s = 0; s < 3; s++) {
#pragma unroll
        for (int r = 0; r < 4; r++) cp16(sA[s] + la_rel[r], Ab + la_off[r] + s * TBKH);
#pragma unroll
        for (int r = 0; r < 8; r++) cp16(sB[s] + lb_rel[r], Bb + lb_off[r] + s * TBKH);
        CP_COMMIT();
    }

    uint32_t af[2][4][4], bf[2][4][4];

    int buf = 0;
    for (int it = 0; it < NIT; it++) {
        CP_WAIT(2);        // stage `it` landed (3 groups pending at loop top)
        __syncthreads();   // visibility + readers of reused slot done

        if (it + 3 < NIT) {
            const int k0 = (it + 3) * TBKH;
            const int ns = (buf + 3) & 3;   // slot last read at iter it-1
#pragma unroll
            for (int r = 0; r < 4; r++) cp16(sA[ns] + la_rel[r], Ab + la_off[r] + k0);
#pragma unroll
            for (int r = 0; r < 8; r++) cp16(sB[ns] + lb_rel[r], Bb + lb_off[r] + k0);
        }
        CP_COMMIT();

        const uint32_t sa = sA[buf], sb = sB[buf];

        // load frags for ks=0 into slot 0
#pragma unroll
        for (int mt = 0; mt < 4; mt++)
            ldsm_x4(sa + a_rowOff[mt] + (((0 * 2 + abit) ^ a_rx[mt]) << 4),
                    af[0][mt][0], af[0][mt][1], af[0][mt][2], af[0][mt][3]);
#pragma unroll
        for (int ntp = 0; ntp < 4; ntp++)
            ldsm_x4(sb + b_rowOff[ntp] + (((0 * 2 + bbit) ^ b_rx[ntp]) << 4),
                    bf[0][ntp][0], bf[0][ntp][1], bf[0][ntp][2], bf[0][ntp][3]);

#pragma unroll
        for (int ks = 0; ks < 4; ks++) {
            const int cur = ks & 1, nxt = (ks + 1) & 1;
            if (ks < 3) {
                int ch_a = (ks + 1) * 2 + abit;
                int ch_b = (ks + 1) * 2 + bbit;
#pragma unroll
                for (int mt = 0; mt < 4; mt++)
                    ldsm_x4(sa + a_rowOff[mt] + ((ch_a ^ a_rx[mt]) << 4),
                            af[nxt][mt][0], af[nxt][mt][1], af[nxt][mt][2], af[nxt][mt][3]);
#pragma unroll
                for (int ntp = 0; ntp < 4; ntp++)
                    ldsm_x4(sb + b_rowOff[ntp] + ((ch_b ^ b_rx[ntp]) << 4),
                            bf[nxt][ntp][0], bf[nxt][ntp][1], bf[nxt][ntp][2], bf[nxt][ntp][3]);
            }
#pragma unroll
            for (int mt = 0; mt < 4; mt++)
#pragma unroll
                for (int nt = 0; nt < 8; nt++) {
                    const uint32_t* bp = &bf[cur][nt >> 1][(nt & 1) * 2];
                    mma_f16(c[mt][nt][0], c[mt][nt][1], c[mt][nt][2], c[mt][nt][3],
                            af[cur][mt][0], af[cur][mt][1], af[cur][mt][2], af[cur][mt][3],
                            bp[0], bp[1]);
                }
        }
        buf = (buf + 1) & 3;
    }

    const int rql = lane >> 2;
    const int cpl = (lane & 3) * 2;
#pragma unroll
    for (int mt = 0; mt < 4; mt++) {
        int rg = row0 + warp_m * 64 + mt * 16 + rql;
#pragma unroll
        for (int nt = 0; nt < 8; nt++) {
            int cg = col0 + warp_n * 64 + nt * 8 + cpl;
            if (HALF_OUT) {
                __half* C = (__half*)Cv;
                *(uint32_t*)(C + (size_t)rg * N + cg)       = pack_h2(c[mt][nt][0], c[mt][nt][1]);
                *(uint32_t*)(C + (size_t)(rg + 8) * N + cg) = pack_h2(c[mt][nt][2], c[mt][nt][3]);
            } else {
                float* C = (float*)Cv;
                float2 v0 = {c[mt][nt][0], c[mt][nt][1]};
                float2 v1 = {c[mt][nt][2], c[mt][nt][3]};
                *(float2*)(C + (size_t)rg * N + cg)       = v0;
                *(float2*)(C + (size_t)(rg + 8) * N + cg) = v1;
            }
        }
    }
}

// ---------------------------------------------------------------------------
// fp16 causal flash attention (unchanged from R13 — passing at 322.6)
// ---------------------------------------------------------------------------
#define ATT_SCALE 0.18033688f
#define ATT_STAGE_BYTES 32768
#define ATT_SMEM  (16384 + 3 * ATT_STAGE_BYTES)   // 114688
#define ONES_H2   0x3C003C00u

__global__ __launch_bounds__(256, 2)
void attn_f16(const __half* __restrict__ qkv, __half* __restrict__ y) {
    extern __shared__ uint32_t smu[];
    char* smc = (char*)smu;
    const uint32_t qs_base = smem_u32(smu);
    const uint32_t st_base = qs_base + 16384;

    const int tid  = threadIdx.x;
    const int lane = tid & 31;
    const int w    = tid >> 5;
    const int qi   = (S_LEN / 128 - 1) - blockIdx.x;
    const int h    = blockIdx.y;
    const int b    = blockIdx.z;
    const int q0   = qi * 128;

    const __half* qb = qkv + (size_t)b * S_LEN * D3 + h * DH;
    const __half* kb = qb + D_MODEL;
    const __half* vb = qb + 2 * D_MODEL;

    int l_row[4], l_chk[4];
    uint32_t l_rel[4];
#pragma unroll
    for (int r = 0; r < 4; r++) {
        int idx = tid + 256 * r;
        l_row[r] = idx >> 3; l_chk[r] = idx & 7;
        l_rel[r] = (uint32_t)(l_row[r] * 128 + ((l_chk[r] ^ (l_row[r] & 7)) << 4));
    }

    const int njb = qi + 1;

    {
        const uint32_t kd = st_base, vd = st_base + 16384;
#pragma unroll
        for (int r = 0; r < 4; r++) {
            cp16(kd + l_rel[r], kb + (size_t)l_row[r] * D3 + l_chk[r] * 8);
            cp16(vd + l_rel[r], vb + (size_t)l_row[r] * D3 + l_chk[r] * 8);
        }
        CP_COMMIT();
    }
    if (njb > 1) {
        const uint32_t kd = st_base + ATT_STAGE_BYTES, vd = kd + 16384;
#pragma unroll
        for (int r = 0; r < 4; r++) {
            cp16(kd + l_rel[r], kb + (size_t)(128 + l_row[r]) * D3 + l_chk[r] * 8);
            cp16(vd + l_rel[r], vb + (size_t)(128 + l_row[r]) * D3 + l_chk[r] * 8);
        }
    }
    CP_COMMIT();

#pragma unroll
    for (int r = 0; r < 4; r++) {
        int idx = tid + 256 * r, row = idx >> 3, ch = idx & 7;
        uint4 raw = *(const uint4*)(qb + (size_t)(q0 + row) * D3 + ch * 8);
        uint32_t* rp = (uint32_t*)&raw;
        uint4 outv;
        uint32_t* op = (uint32_t*)&outv;
#pragma unroll
        for (int j = 0; j < 4; j++) {
            __half2 hv = *(__half2*)&rp[j];
            float2 f = __half22float2(hv);
            op[j] = pack_h2(f.x * ATT_SCALE, f.y * ATT_SCALE);
        }
        *(uint4*)(smc + row * 128 + ((ch ^ (row & 7)) << 4)) = outv;
    }
    __syncthreads();

    const int mat = lane >> 3, rr = lane & 7;
    uint32_t qf[4][4];
    {
        int rowA = w * 16 + ((mat & 1) << 3) + rr;
        int rbase = rowA * 128;
        int rx = rowA & 7;
#pragma unroll
        for (int ks = 0; ks < 4; ks++) {
            int ch = ks * 2 + (mat >> 1);
            ldsm_x4(qs_base + rbase + ((ch ^ rx) << 4), qf[ks][0], qf[ks][1], qf[ks][2], qf[ks][3]);
        }
    }
    uint32_t krowOff[4]; int krx[4];
#pragma unroll
    for (int ntp = 0; ntp < 4; ntp++) {
        int rowB = ntp * 16 + ((mat >> 1) << 3) + rr;
        krowOff[ntp] = (uint32_t)(rowB * 128);
        krx[ntp] = rowB & 7;
    }
    const int kbit = mat & 1;
    uint32_t vrowOff[4]; int vrx[4];
#pragma unroll
    for (int kt = 0; kt < 4; kt++) {
        int rowV = kt * 16 + ((mat & 1) << 3) + rr;
        vrowOff[kt] = (uint32_t)(rowV * 128);
        vrx[kt] = rowV & 7;
    }
    const int vbit = mat >> 1;

    float m_lo = -1e30f, m_hi = -1e30f, l_lo = 0.f, l_hi = 0.f;
    float co[8][4];
#pragma unroll
    for (int i = 0; i < 8; i++)
#pragma unroll
        for (int q = 0; q < 4; q++) co[i][q] = 0.f;

    const int rlo  = q0 + w * 16 + (lane >> 2);
    const int jsel = lane & 3;

    int sbuf = 0;

    for (int jb = 0; jb < njb; jb++) {
        CP_WAIT(1);
        __syncthreads();

        if (jb + 2 < njb) {
            const int kn = (jb + 2) * 128;
            const int ns = (sbuf + 2 >= 3) ? (sbuf - 1) : (sbuf + 2);
            const uint32_t kd = st_base + ns * ATT_STAGE_BYTES, vd = kd + 16384;
#pragma unroll
            for (int r = 0; r < 4; r++) {
                cp16(kd + l_rel[r], kb + (size_t)(kn + l_row[r]) * D3 + l_chk[r] * 8);
                cp16(vd + l_rel[r], vb + (size_t)(kn + l_row[r]) * D3 + l_chk[r] * 8);
            }
        }
        CP_COMMIT();

        const uint32_t stg = st_base + (uint32_t)(sbuf * ATT_STAGE_BYTES);

#pragma unroll
        for (int hh = 0; hh < 2; hh++) {
            const uint32_t kbuf = stg + hh * 8192;
            const uint32_t vbuf = stg + 16384 + hh * 8192;
            const int cbase = jb * 128 + hh * 64;

            float cs[8][4];
#pragma unroll
            for (int i = 0; i < 8; i++)
#pragma unroll
                for (int q = 0; q < 4; q++) cs[i][q] = 0.f;

#pragma unroll
            for (int ks = 0; ks < 4; ks++) {
                uint32_t bfr[4][4];
                int ch = ks * 2 + kbit;
#pragma unroll
                for (int ntp = 0; ntp < 4; ntp++)
                    ldsm_x4(kbuf + krowOff[ntp] + ((ch ^ krx[ntp]) << 4),
                            bfr[ntp][0], bfr[ntp][1], bfr[ntp][2], bfr[ntp][3]);
#pragma unroll
                for (int nt = 0; nt < 8; nt++) {
                    const uint32_t* bp = &bfr[nt >> 1][(nt & 1) * 2];
                    mma_f16(cs[nt][0], cs[nt][1], cs[nt][2], cs[nt][3],
                            qf[ks][0], qf[ks][1], qf[ks][2], qf[ks][3], bp[0], bp[1]);
                }
            }

            if (cbase >= q0) {
#pragma unroll
                for (int nt = 0; nt < 8; nt++) {
                    int cb = cbase + nt * 8 + 2 * jsel;
                    if (cb     > rlo)     cs[nt][0] = -1e30f;
                    if (cb + 1 > rlo)     cs[nt][1] = -1e30f;
                    if (cb     > rlo + 8) cs[nt][2] = -1e30f;
                    if (cb + 1 > rlo + 8) cs[nt][3] = -1e30f;
                }
            }

            float ml = -1e30f, mh = -1e30f;
#pragma unroll
            for (int nt = 0; nt < 8; nt++) {
                ml = fmaxf(ml, fmaxf(cs[nt][0], cs[nt][1]));
                mh = fmaxf(mh, fmaxf(cs[nt][2], cs[nt][3]));
            }
            ml = fmaxf(ml, __shfl_xor_sync(0xffffffffu, ml, 1));
            ml = fmaxf(ml, __shfl_xor_sync(0xffffffffu, ml, 2));
            mh = fmaxf(mh, __shfl_xor_sync(0xffffffffu, mh, 1));
            mh = fmaxf(mh, __shfl_xor_sync(0xffffffffu, mh, 2));
            float Ml = fmaxf(m_lo, ml), Mh = fmaxf(m_hi, mh);
            float al = ex2f(m_lo - Ml), ah = ex2f(m_hi - Mh);
            m_lo = Ml; m_hi = Mh;

            uint32_t pp[8][2];
#pragma unroll
            for (int nt = 0; nt < 8; nt++) {
                pp[nt][0] = h2ex2(pack_h2(cs[nt][0] - Ml, cs[nt][1] - Ml));
                pp[nt][1] = h2ex2(pack_h2(cs[nt][2] - Mh, cs[nt][3] - Mh));
            }

            float csum0 = 0.f, csum1 = 0.f, csum2 = 0.f, csum3 = 0.f;
#pragma unroll
            for (int kt = 0; kt < 4; kt++)
                mma_f16(csum0, csum1, csum2, csum3,
                        pp[2 * kt][0], pp[2 * kt][1], pp[2 * kt + 1][0], pp[2 * kt + 1][1],
                        ONES_H2, ONES_H2);
            l_lo = l_lo * al + csum0;
            l_hi = l_hi * ah + csum2;

#pragma unroll
            for (int i = 0; i < 8; i++) {
                co[i][0] *= al; co[i][1] *= al; co[i][2] *= ah; co[i][3] *= ah;
            }

#pragma unroll
            for (int kt = 0; kt < 4; kt++) {
                uint32_t pa0 = pp[2 * kt][0];
                uint32_t pa1 = pp[2 * kt][1];
                uint32_t pa2 = pp[2 * kt + 1][0];
                uint32_t pa3 = pp[2 * kt + 1][1];

#pragma unroll
                for (int ntp = 0; ntp < 4; ntp++) {
                    uint32_t bf0, bf1, bf2, bf3;
                    int ch = ntp * 2 + vbit;
                    ldsm_x4t(vbuf + vrowOff[kt] + ((ch ^ vrx[kt]) << 4), bf0, bf1, bf2, bf3);
                    mma_f16(co[2 * ntp][0], co[2 * ntp][1], co[2 * ntp][2], co[2 * ntp][3],
                            pa0, pa1, pa2, pa3, bf0, bf1);
                    mma_f16(co[2 * ntp + 1][0], co[2 * ntp + 1][1], co[2 * ntp + 1][2], co[2 * ntp + 1][3],
                            pa0, pa1, pa2, pa3, bf2, bf3);
                }
            }
        }

        sbuf = (sbuf + 1 == 3) ? 0 : sbuf + 1;
    }

    const float il = 1.0f / l_lo, ih = 1.0f / l_hi;
    __half* yb = y + ((size_t)b * S_LEN + q0 + w * 16 + (lane >> 2)) * D_MODEL + h * DH + 2 * jsel;
#pragma unroll
    for (int nt = 0; nt < 8; nt++) {
        *(uint32_t*)(yb + nt * 8)                       = pack_h2(co[nt][0] * il, co[nt][1] * il);
        *(uint32_t*)(yb + nt * 8 + 8 * (size_t)D_MODEL) = pack_h2(co[nt][2] * ih, co[nt][3] * ih);
    }
}

// ---------------------------------------------------------------------------
extern "C" void kernel_launch(void* const* d_in, const int* in_sizes, int n_in,
                              void* d_out, int out_size) {
    const float* x      = (const float*)d_in[0];
    const float* w_attn = (const float*)d_in[1];
    const float* w_proj = (const float*)d_in[2];
    float* out = (float*)d_out;

    __half *qkv, *yb, *xc, *wac, *wpc;
    cudaGetSymbolAddress((void**)&qkv, g_qkv);
    cudaGetSymbolAddress((void**)&yb, g_y);
    cudaGetSymbolAddress((void**)&xc, g_xc);
    cudaGetSymbolAddress((void**)&wac, g_wac);
    cudaGetSymbolAddress((void**)&wpc, g_wpc);

    cudaFuncSetAttribute(gemm_f16<true>,  cudaFuncAttributeMaxDynamicSharedMemorySize, GEMM_SMEM);
    cudaFuncSetAttribute(gemm_f16<false>, cudaFuncAttributeMaxDynamicSharedMemorySize, GEMM_SMEM);
    cudaFuncSetAttribute(attn_f16, cudaFuncAttributeMaxDynamicSharedMemorySize, ATT_SMEM);

    round_all<<<(RND_TOTAL + 255) / 256, 256>>>(x, w_attn, w_proj);

    dim3 g1(D3 / TBN, M_ROWS / TBM);
    gemm_f16<true><<<g1, 256, GEMM_SMEM>>>(xc, wac, qkv, M_ROWS, D3, D_MODEL);

    dim3 ga(S_LEN / 128, N_HEADS, BATCH);
    attn_f16<<<ga, 256, ATT_SMEM>>>(qkv, yb);

    dim3 g2(D_MODEL / TBN, M_ROWS / TBM);
    gemm_f16<false><<<g2, 256, GEMM_SMEM>>>(yb, wpc, out, M_ROWS, D_MODEL, D_MODEL);
}

// round 15
// speedup vs baseline: 1.0806x; 1.0806x over previous
#include <cuda_runtime.h>
#include <cuda_fp16.h>
#include <cstdint>
#include <cstddef>

// ---------------------------------------------------------------------------
// CausalSelfAttention: out = proj( causal_attn( x @ Wqkv^T ) )
// fp16 mma.sync m16n8k16. GEMM: 128x128 tile, warp 64x32, K-stage 64, 3-stage
// cp.async ring, 2 CTA/SM. Attention: fp16 flash, 128-kv stages (two 64-col
// softmax passes), f16x2 exp, ones-MMA row sums. Fused pre-round kernel.
// (R13 configuration — best verified.)
// ---------------------------------------------------------------------------

#define BATCH   4
#define S_LEN   2048
#define D_MODEL 1024
#define D3      3072
#define N_HEADS 16
#define DH      64
#define M_ROWS  (BATCH * S_LEN)   // 8192

__device__ __half g_qkv[(size_t)M_ROWS * D3];
__device__ __half g_y[(size_t)M_ROWS * D_MODEL];
__device__ __half g_xc[(size_t)M_ROWS * D_MODEL];
__device__ __half g_wac[(size_t)D3 * D_MODEL];
__device__ __half g_wpc[(size_t)D_MODEL * D_MODEL];

// ---- helpers ----------------------------------------------------------------
__device__ __forceinline__ uint32_t pack_h2(float a, float b) {
    __half2 h = __floats2half2_rn(a, b);
    return *(uint32_t*)&h;
}
__device__ __forceinline__ float ex2f(float x) {
    float r;
    asm("ex2.approx.ftz.f32 %0, %1;" : "=f"(r) : "f"(x));
    return r;
}
__device__ __forceinline__ uint32_t h2ex2(uint32_t x) {
    uint32_t r;
    asm("ex2.approx.f16x2 %0, %1;" : "=r"(r) : "r"(x));
    return r;
}
__device__ __forceinline__ void ldsm_x4(uint32_t addr, uint32_t& r0, uint32_t& r1,
                                        uint32_t& r2, uint32_t& r3) {
    asm volatile("ldmatrix.sync.aligned.m8n8.x4.shared.b16 {%0,%1,%2,%3}, [%4];"
                 : "=r"(r0), "=r"(r1), "=r"(r2), "=r"(r3) : "r"(addr));
}
__device__ __forceinline__ void ldsm_x4t(uint32_t addr, uint32_t& r0, uint32_t& r1,
                                         uint32_t& r2, uint32_t& r3) {
    asm volatile("ldmatrix.sync.aligned.m8n8.x4.trans.shared.b16 {%0,%1,%2,%3}, [%4];"
                 : "=r"(r0), "=r"(r1), "=r"(r2), "=r"(r3) : "r"(addr));
}
__device__ __forceinline__ void mma_f16(float& c0, float& c1, float& c2, float& c3,
                                        uint32_t a0, uint32_t a1, uint32_t a2, uint32_t a3,
                                        uint32_t b0, uint32_t b1) {
    asm volatile("mma.sync.aligned.m16n8k16.row.col.f32.f16.f16.f32 "
                 "{%0,%1,%2,%3}, {%4,%5,%6,%7}, {%8,%9}, {%0,%1,%2,%3};"
                 : "+f"(c0), "+f"(c1), "+f"(c2), "+f"(c3)
                 : "r"(a0), "r"(a1), "r"(a2), "r"(a3), "r"(b0), "r"(b1));
}
__device__ __forceinline__ void cp16(uint32_t dst, const void* src) {
    asm volatile("cp.async.cg.shared.global [%0], [%1], 16;" :: "r"(dst), "l"(src));
}
#define CP_COMMIT() asm volatile("cp.async.commit_group;")
#define CP_WAIT(n)  asm volatile("cp.async.wait_group %0;" :: "n"(n))

__device__ __forceinline__ uint32_t smem_u32(const void* p) {
    return (uint32_t)__cvta_generic_to_shared(p);
}

// ---------------------------------------------------------------------------
// Fused pre-round fp32 -> fp16 for x, w_attn, w_proj (one launch)
// ---------------------------------------------------------------------------
#define XC_N4  (M_ROWS * D_MODEL / 4)
#define WAC_N4 (D3 * D_MODEL / 4)
#define WPC_N4 (D_MODEL * D_MODEL / 4)
#define RND_TOTAL (XC_N4 + WAC_N4 + WPC_N4)

__global__ void round_all(const float* __restrict__ x, const float* __restrict__ wa,
                          const float* __restrict__ wp) {
    int i = blockIdx.x * blockDim.x + threadIdx.x;
    if (i >= RND_TOTAL) return;
    const float* src;
    __half* dst;
    int j;
    if (i < XC_N4)                { src = x;  dst = g_xc;  j = i; }
    else if (i < XC_N4 + WAC_N4)  { src = wa; dst = g_wac; j = i - XC_N4; }
    else                          { src = wp; dst = g_wpc; j = i - XC_N4 - WAC_N4; }
    float4 v = ((const float4*)src)[j];
    uint2 r = {pack_h2(v.x, v.y), pack_h2(v.z, v.w)};
    ((uint2*)dst)[j] = r;
}

// ---------------------------------------------------------------------------
// fp16 GEMM (NT): C[M,N] = A[M,K] @ B[N,K]^T
// Block 128x128, K-stage 64 halfs (128B rows, swizzle ch^(row&7)), 8 warps 2x4,
// warp 64x32. 3-stage ring, CP_WAIT(1) -> sync -> prefetch -> commit -> compute.
// ---------------------------------------------------------------------------
#define TBM 128
#define TBN 128
#define TBKH 64
#define GSTG 3
#define G_TILE_BYTES 16384
#define G_STAGE_BYTES (2 * G_TILE_BYTES)
#define GEMM_SMEM (GSTG * G_STAGE_BYTES)   // 98304

template <bool HALF_OUT>
__global__ __launch_bounds__(256, 2)
void gemm_f16(const __half* __restrict__ A, const __half* __restrict__ B,
              void* __restrict__ Cv, int M, int N, int K) {
    extern __shared__ uint32_t sh[];

    const int tid    = threadIdx.x;
    const int lane   = tid & 31;
    const int warp   = tid >> 5;
    const int warp_m = warp >> 2;
    const int warp_n = warp & 3;
    const int row0   = blockIdx.y * TBM;
    const int col0   = blockIdx.x * TBN;

    const __half* Ab = A + (size_t)row0 * K;
    const __half* Bb = B + (size_t)col0 * K;

    const uint32_t base = smem_u32(sh);
    uint32_t sA[GSTG], sB[GSTG];
#pragma unroll
    for (int s = 0; s < GSTG; s++) { sA[s] = base + s * G_STAGE_BYTES; sB[s] = sA[s] + G_TILE_BYTES; }

    uint32_t l_rel[4], l_soff[4];
#pragma unroll
    for (int r = 0; r < 4; r++) {
        int idx = tid + 256 * r, row = idx >> 3, c = idx & 7;
        l_rel[r]  = (uint32_t)(row * 128 + ((c ^ (row & 7)) << 4));
        l_soff[r] = (uint32_t)(row * K + c * 8);
    }

    const int mat = lane >> 3, rr = lane & 7;
    uint32_t a_rowOff[4]; int a_rx[4];
#pragma unroll
    for (int mt = 0; mt < 4; mt++) {
        int row = warp_m * 64 + mt * 16 + ((mat & 1) << 3) + rr;
        a_rowOff[mt] = (uint32_t)(row * 128);
        a_rx[mt] = row & 7;
    }
    const int abit = mat >> 1;
    uint32_t b_rowOff[2]; int b_rx[2];
#pragma unroll
    for (int ntp = 0; ntp < 2; ntp++) {
        int row = warp_n * 32 + ntp * 16 + ((mat >> 1) << 3) + rr;
        b_rowOff[ntp] = (uint32_t)(row * 128);
        b_rx[ntp] = row & 7;
    }
    const int bbit = mat & 1;

    float c[4][4][4];
#pragma unroll
    for (int i = 0; i < 4; i++)
#pragma unroll
        for (int j = 0; j < 4; j++)
#pragma unroll
            for (int q = 0; q < 4; q++) c[i][j][q] = 0.f;

    const int NIT = K / TBKH;   // 16

#pragma unroll
    for (int s = 0; s < 2; s++) {
#pragma unroll
        for (int r = 0; r < 4; r++) {
            cp16(sA[s] + l_rel[r], Ab + l_soff[r] + s * TBKH);
            cp16(sB[s] + l_rel[r], Bb + l_soff[r] + s * TBKH);
        }
        CP_COMMIT();
    }

    int buf = 0;
    for (int it = 0; it < NIT; it++) {
        CP_WAIT(1);
        __syncthreads();

        if (it + 2 < NIT) {
            const int k0 = (it + 2) * TBKH;
            const int ns = (buf + 2 >= GSTG) ? (buf + 2 - GSTG) : (buf + 2);
#pragma unroll
            for (int r = 0; r < 4; r++) {
                cp16(sA[ns] + l_rel[r], Ab + l_soff[r] + k0);
                cp16(sB[ns] + l_rel[r], Bb + l_soff[r] + k0);
            }
        }
        CP_COMMIT();

#pragma unroll
        for (int ks = 0; ks < 4; ks++) {
            uint32_t af[4][4];
#pragma unroll
            for (int mt = 0; mt < 4; mt++) {
                int ch = ks * 2 + abit;
                ldsm_x4(sA[buf] + a_rowOff[mt] + ((ch ^ a_rx[mt]) << 4),
                        af[mt][0], af[mt][1], af[mt][2], af[mt][3]);
            }
            uint32_t bf[2][4];
#pragma unroll
            for (int ntp = 0; ntp < 2; ntp++) {
                int ch = ks * 2 + bbit;
                ldsm_x4(sB[buf] + b_rowOff[ntp] + ((ch ^ b_rx[ntp]) << 4),
                        bf[ntp][0], bf[ntp][1], bf[ntp][2], bf[ntp][3]);
            }
#pragma unroll
            for (int mt = 0; mt < 4; mt++)
#pragma unroll
                for (int nt = 0; nt < 4; nt++) {
                    const uint32_t* bp = &bf[nt >> 1][(nt & 1) * 2];
                    mma_f16(c[mt][nt][0], c[mt][nt][1], c[mt][nt][2], c[mt][nt][3],
                            af[mt][0], af[mt][1], af[mt][2], af[mt][3], bp[0], bp[1]);
                }
        }
        buf = (buf + 1 == GSTG) ? 0 : buf + 1;
    }

    const int rql = lane >> 2;
    const int cpl = (lane & 3) * 2;
#pragma unroll
    for (int mt = 0; mt < 4; mt++) {
        int rg = row0 + warp_m * 64 + mt * 16 + rql;
#pragma unroll
        for (int nt = 0; nt < 4; nt++) {
            int cg = col0 + warp_n * 32 + nt * 8 + cpl;
            if (HALF_OUT) {
                __half* C = (__half*)Cv;
                *(uint32_t*)(C + (size_t)rg * N + cg)       = pack_h2(c[mt][nt][0], c[mt][nt][1]);
                *(uint32_t*)(C + (size_t)(rg + 8) * N + cg) = pack_h2(c[mt][nt][2], c[mt][nt][3]);
            } else {
                float* C = (float*)Cv;
                float2 v0 = {c[mt][nt][0], c[mt][nt][1]};
                float2 v1 = {c[mt][nt][2], c[mt][nt][3]};
                *(float2*)(C + (size_t)rg * N + cg)       = v0;
                *(float2*)(C + (size_t)(rg + 8) * N + cg) = v1;
            }
        }
    }
}

// ---------------------------------------------------------------------------
// fp16 causal flash attention: 128-kv pipeline stages, two 64-col softmax
// passes per stage. 3-stage ring. SMEM: Q 16K + 3x(K 16K + V 16K) = 112KB.
// ---------------------------------------------------------------------------
#define ATT_SCALE 0.18033688f
#define ATT_STAGE_BYTES 32768
#define ATT_SMEM  (16384 + 3 * ATT_STAGE_BYTES)   // 114688
#define ONES_H2   0x3C003C00u

__global__ __launch_bounds__(256, 2)
void attn_f16(const __half* __restrict__ qkv, __half* __restrict__ y) {
    extern __shared__ uint32_t smu[];
    char* smc = (char*)smu;
    const uint32_t qs_base = smem_u32(smu);
    const uint32_t st_base = qs_base + 16384;

    const int tid  = threadIdx.x;
    const int lane = tid & 31;
    const int w    = tid >> 5;
    const int qi   = (S_LEN / 128 - 1) - blockIdx.x;
    const int h    = blockIdx.y;
    const int b    = blockIdx.z;
    const int q0   = qi * 128;

    const __half* qb = qkv + (size_t)b * S_LEN * D3 + h * DH;
    const __half* kb = qb + D_MODEL;
    const __half* vb = qb + 2 * D_MODEL;

    int l_row[4], l_chk[4];
    uint32_t l_rel[4];
#pragma unroll
    for (int r = 0; r < 4; r++) {
        int idx = tid + 256 * r;
        l_row[r] = idx >> 3; l_chk[r] = idx & 7;
        l_rel[r] = (uint32_t)(l_row[r] * 128 + ((l_chk[r] ^ (l_row[r] & 7)) << 4));
    }

    const int njb = qi + 1;

    {
        const uint32_t kd = st_base, vd = st_base + 16384;
#pragma unroll
        for (int r = 0; r < 4; r++) {
            cp16(kd + l_rel[r], kb + (size_t)l_row[r] * D3 + l_chk[r] * 8);
            cp16(vd + l_rel[r], vb + (size_t)l_row[r] * D3 + l_chk[r] * 8);
        }
        CP_COMMIT();
    }
    if (njb > 1) {
        const uint32_t kd = st_base + ATT_STAGE_BYTES, vd = kd + 16384;
#pragma unroll
        for (int r = 0; r < 4; r++) {
            cp16(kd + l_rel[r], kb + (size_t)(128 + l_row[r]) * D3 + l_chk[r] * 8);
            cp16(vd + l_rel[r], vb + (size_t)(128 + l_row[r]) * D3 + l_chk[r] * 8);
        }
    }
    CP_COMMIT();

#pragma unroll
    for (int r = 0; r < 4; r++) {
        int idx = tid + 256 * r, row = idx >> 3, ch = idx & 7;
        uint4 raw = *(const uint4*)(qb + (size_t)(q0 + row) * D3 + ch * 8);
        uint32_t* rp = (uint32_t*)&raw;
        uint4 outv;
        uint32_t* op = (uint32_t*)&outv;
#pragma unroll
        for (int j = 0; j < 4; j++) {
            __half2 hv = *(__half2*)&rp[j];
            float2 f = __half22float2(hv);
            op[j] = pack_h2(f.x * ATT_SCALE, f.y * ATT_SCALE);
        }
        *(uint4*)(smc + row * 128 + ((ch ^ (row & 7)) << 4)) = outv;
    }
    __syncthreads();

    const int mat = lane >> 3, rr = lane & 7;
    uint32_t qf[4][4];
    {
        int rowA = w * 16 + ((mat & 1) << 3) + rr;
        int rbase = rowA * 128;
        int rx = rowA & 7;
#pragma unroll
        for (int ks = 0; ks < 4; ks++) {
            int ch = ks * 2 + (mat >> 1);
            ldsm_x4(qs_base + rbase + ((ch ^ rx) << 4), qf[ks][0], qf[ks][1], qf[ks][2], qf[ks][3]);
        }
    }
    uint32_t krowOff[4]; int krx[4];
#pragma unroll
    for (int ntp = 0; ntp < 4; ntp++) {
        int rowB = ntp * 16 + ((mat >> 1) << 3) + rr;
        krowOff[ntp] = (uint32_t)(rowB * 128);
        krx[ntp] = rowB & 7;
    }
    const int kbit = mat & 1;
    uint32_t vrowOff[4]; int vrx[4];
#pragma unroll
    for (int kt = 0; kt < 4; kt++) {
        int rowV = kt * 16 + ((mat & 1) << 3) + rr;
        vrowOff[kt] = (uint32_t)(rowV * 128);
        vrx[kt] = rowV & 7;
    }
    const int vbit = mat >> 1;

    float m_lo = -1e30f, m_hi = -1e30f, l_lo = 0.f, l_hi = 0.f;
    float co[8][4];
#pragma unroll
    for (int i = 0; i < 8; i++)
#pragma unroll
        for (int q = 0; q < 4; q++) co[i][q] = 0.f;

    const int rlo  = q0 + w * 16 + (lane >> 2);
    const int jsel = lane & 3;

    int sbuf = 0;

    for (int jb = 0; jb < njb; jb++) {
        CP_WAIT(1);
        __syncthreads();

        if (jb + 2 < njb) {
            const int kn = (jb + 2) * 128;
            const int ns = (sbuf + 2 >= 3) ? (sbuf - 1) : (sbuf + 2);
            const uint32_t kd = st_base + ns * ATT_STAGE_BYTES, vd = kd + 16384;
#pragma unroll
            for (int r = 0; r < 4; r++) {
                cp16(kd + l_rel[r], kb + (size_t)(kn + l_row[r]) * D3 + l_chk[r] * 8);
                cp16(vd + l_rel[r], vb + (size_t)(kn + l_row[r]) * D3 + l_chk[r] * 8);
            }
        }
        CP_COMMIT();

        const uint32_t stg = st_base + (uint32_t)(sbuf * ATT_STAGE_BYTES);

#pragma unroll
        for (int hh = 0; hh < 2; hh++) {
            const uint32_t kbuf = stg + hh * 8192;
            const uint32_t vbuf = stg + 16384 + hh * 8192;
            const int cbase = jb * 128 + hh * 64;

            float cs[8][4];
#pragma unroll
            for (int i = 0; i < 8; i++)
#pragma unroll
                for (int q = 0; q < 4; q++) cs[i][q] = 0.f;

#pragma unroll
            for (int ks = 0; ks < 4; ks++) {
                uint32_t bfr[4][4];
                int ch = ks * 2 + kbit;
#pragma unroll
                for (int ntp = 0; ntp < 4; ntp++)
                    ldsm_x4(kbuf + krowOff[ntp] + ((ch ^ krx[ntp]) << 4),
                            bfr[ntp][0], bfr[ntp][1], bfr[ntp][2], bfr[ntp][3]);
#pragma unroll
                for (int nt = 0; nt < 8; nt++) {
                    const uint32_t* bp = &bfr[nt >> 1][(nt & 1) * 2];
                    mma_f16(cs[nt][0], cs[nt][1], cs[nt][2], cs[nt][3],
                            qf[ks][0], qf[ks][1], qf[ks][2], qf[ks][3], bp[0], bp[1]);
                }
            }

            if (cbase >= q0) {
#pragma unroll
                for (int nt = 0; nt < 8; nt++) {
                    int cb = cbase + nt * 8 + 2 * jsel;
                    if (cb     > rlo)     cs[nt][0] = -1e30f;
                    if (cb + 1 > rlo)     cs[nt][1] = -1e30f;
                    if (cb     > rlo + 8) cs[nt][2] = -1e30f;
                    if (cb + 1 > rlo + 8) cs[nt][3] = -1e30f;
                }
            }

            float ml = -1e30f, mh = -1e30f;
#pragma unroll
            for (int nt = 0; nt < 8; nt++) {
                ml = fmaxf(ml, fmaxf(cs[nt][0], cs[nt][1]));
                mh = fmaxf(mh, fmaxf(cs[nt][2], cs[nt][3]));
            }
            ml = fmaxf(ml, __shfl_xor_sync(0xffffffffu, ml, 1));
            ml = fmaxf(ml, __shfl_xor_sync(0xffffffffu, ml, 2));
            mh = fmaxf(mh, __shfl_xor_sync(0xffffffffu, mh, 1));
            mh = fmaxf(mh, __shfl_xor_sync(0xffffffffu, mh, 2));
            float Ml = fmaxf(m_lo, ml), Mh = fmaxf(m_hi, mh);
            float al = ex2f(m_lo - Ml), ah = ex2f(m_hi - Mh);
            m_lo = Ml; m_hi = Mh;

            uint32_t pp[8][2];
#pragma unroll
            for (int nt = 0; nt < 8; nt++) {
                pp[nt][0] = h2ex2(pack_h2(cs[nt][0] - Ml, cs[nt][1] - Ml));
                pp[nt][1] = h2ex2(pack_h2(cs[nt][2] - Mh, cs[nt][3] - Mh));
            }

            float csum0 = 0.f, csum1 = 0.f, csum2 = 0.f, csum3 = 0.f;
#pragma unroll
            for (int kt = 0; kt < 4; kt++)
                mma_f16(csum0, csum1, csum2, csum3,
                        pp[2 * kt][0], pp[2 * kt][1], pp[2 * kt + 1][0], pp[2 * kt + 1][1],
                        ONES_H2, ONES_H2);
            l_lo = l_lo * al + csum0;
            l_hi = l_hi * ah + csum2;

#pragma unroll
            for (int i = 0; i < 8; i++) {
                co[i][0] *= al; co[i][1] *= al; co[i][2] *= ah; co[i][3] *= ah;
            }

#pragma unroll
            for (int kt = 0; kt < 4; kt++) {
                uint32_t pa0 = pp[2 * kt][0];
                uint32_t pa1 = pp[2 * kt][1];
                uint32_t pa2 = pp[2 * kt + 1][0];
                uint32_t pa3 = pp[2 * kt + 1][1];

#pragma unroll
                for (int ntp = 0; ntp < 4; ntp++) {
                    uint32_t bf0, bf1, bf2, bf3;
                    int ch = ntp * 2 + vbit;
                    ldsm_x4t(vbuf + vrowOff[kt] + ((ch ^ vrx[kt]) << 4), bf0, bf1, bf2, bf3);
                    mma_f16(co[2 * ntp][0], co[2 * ntp][1], co[2 * ntp][2], co[2 * ntp][3],
                            pa0, pa1, pa2, pa3, bf0, bf1);
                    mma_f16(co[2 * ntp + 1][0], co[2 * ntp + 1][1], co[2 * ntp + 1][2], co[2 * ntp + 1][3],
                            pa0, pa1, pa2, pa3, bf2, bf3);
                }
            }
        }

        sbuf = (sbuf + 1 == 3) ? 0 : sbuf + 1;
    }

    const float il = 1.0f / l_lo, ih = 1.0f / l_hi;
    __half* yb = y + ((size_t)b * S_LEN + q0 + w * 16 + (lane >> 2)) * D_MODEL + h * DH + 2 * jsel;
#pragma unroll
    for (int nt = 0; nt < 8; nt++) {
        *(uint32_t*)(yb + nt * 8)                       = pack_h2(co[nt][0] * il, co[nt][1] * il);
        *(uint32_t*)(yb + nt * 8 + 8 * (size_t)D_MODEL) = pack_h2(co[nt][2] * ih, co[nt][3] * ih);
    }
}

// ---------------------------------------------------------------------------
extern "C" void kernel_launch(void* const* d_in, const int* in_sizes, int n_in,
                              void* d_out, int out_size) {
    const float* x      = (const float*)d_in[0];
    const float* w_attn = (const float*)d_in[1];
    const float* w_proj = (const float*)d_in[2];
    float* out = (float*)d_out;

    __half *qkv, *yb, *xc, *wac, *wpc;
    cudaGetSymbolAddress((void**)&qkv, g_qkv);
    cudaGetSymbolAddress((void**)&yb, g_y);
    cudaGetSymbolAddress((void**)&xc, g_xc);
    cudaGetSymbolAddress((void**)&wac, g_wac);
    cudaGetSymbolAddress((void**)&wpc, g_wpc);

    cudaFuncSetAttribute(gemm_f16<true>,  cudaFuncAttributeMaxDynamicSharedMemorySize, GEMM_SMEM);
    cudaFuncSetAttribute(gemm_f16<false>, cudaFuncAttributeMaxDynamicSharedMemorySize, GEMM_SMEM);
    cudaFuncSetAttribute(attn_f16, cudaFuncAttributeMaxDynamicSharedMemorySize, ATT_SMEM);

    round_all<<<(RND_TOTAL + 255) / 256, 256>>>(x, w_attn, w_proj);

    dim3 g1(D3 / TBN, M_ROWS / TBM);
    gemm_f16<true><<<g1, 256, GEMM_SMEM>>>(xc, wac, qkv, M_ROWS, D3, D_MODEL);

    dim3 ga(S_LEN / 128, N_HEADS, BATCH);
    attn_f16<<<ga, 256, ATT_SMEM>>>(qkv, yb);

    dim3 g2(D_MODEL / TBN, M_ROWS / TBM);
    gemm_f16<false><<<g2, 256, GEMM_SMEM>>>(yb, wpc, out, M_ROWS, D_MODEL, D_MODEL);
}